// round 13
// baseline (speedup 1.0000x reference)
#include <cuda_runtime.h>
#include <cuda_fp16.h>
#include <math.h>
#include <stdint.h>

#define N_NODES 50000
#define N_EDGES 400000
#define TOT_E   (N_EDGES + N_NODES)
#define IN_CH   128
#define OUT_CH  64
#define HEADS   8
#define F1      (HEADS * OUT_CH)      // 512
#define M_TILES 391

// ---------------- device scratch -------------------------------------------
__device__ __align__(16) __half g_H1h[N_NODES * F1];     // layer-1 features, fp16
__device__ __align__(16) float g_as1[N_NODES * HEADS];
__device__ __align__(16) float g_ad1[N_NODES * HEADS];
__device__ __align__(16) float g_X2[N_NODES * OUT_CH];
__device__ __align__(16) __half g_H2h[N_NODES * OUT_CH];
__device__ __align__(16) float g_as2[N_NODES];
__device__ __align__(16) float g_ad2[N_NODES];
__device__ __align__(16) __half g_w1h[F1 * IN_CH];       // [n][k] transposed, fp16
// CSR by destination
__device__ int g_deg[N_NODES];
__device__ int g_cursor[N_NODES];
__device__ int g_off[N_NODES + 1];
__device__ int g_csr_src[TOT_E];

__device__ __forceinline__ float lrelu(float v) { return v > 0.f ? v : 0.2f * v; }

__device__ __forceinline__ uint32_t smem_u32(const void* p) {
    uint32_t a;
    asm("{ .reg .u64 t; cvta.to.shared.u64 t, %1; cvt.u32.u64 %0, t; }"
        : "=r"(a) : "l"(p));
    return a;
}
__device__ __forceinline__ void ldsm4(uint32_t* r, uint32_t addr) {
    asm volatile("ldmatrix.sync.aligned.m8n8.x4.shared.b16 {%0,%1,%2,%3}, [%4];"
                 : "=r"(r[0]), "=r"(r[1]), "=r"(r[2]), "=r"(r[3]) : "r"(addr));
}
__device__ __forceinline__ void mma16816(float* d, const uint32_t* a,
                                         const uint32_t b0, const uint32_t b1) {
    asm volatile("mma.sync.aligned.m16n8k16.row.col.f32.f16.f16.f32 "
                 "{%0,%1,%2,%3}, {%4,%5,%6,%7}, {%8,%9}, {%0,%1,%2,%3};"
                 : "+f"(d[0]), "+f"(d[1]), "+f"(d[2]), "+f"(d[3])
                 : "r"(a[0]), "r"(a[1]), "r"(a[2]), "r"(a[3]), "r"(b0), "r"(b1));
}

// ---------------- init + CSR build -----------------------------------------
__global__ void k_init() {
    int i = blockIdx.x * blockDim.x + threadIdx.x;
    if (i < N_NODES) { g_deg[i] = 0; g_cursor[i] = 0; }
}
__global__ void k_hist(const int* __restrict__ ei) {
    int e = blockIdx.x * blockDim.x + threadIdx.x;
    if (e >= TOT_E) return;
    int d = (e < N_EDGES) ? ei[N_EDGES + e] : e - N_EDGES;
    atomicAdd(&g_deg[d], 1);
}
__global__ __launch_bounds__(1024) void k_scan() {
    __shared__ int sp[1024];
    int t = threadIdx.x;
    const int CH = (N_NODES + 1023) / 1024;
    int base = t * CH, s = 0;
    for (int i = 0; i < CH; i++) { int idx = base + i; if (idx < N_NODES) s += g_deg[idx]; }
    sp[t] = s;
    __syncthreads();
    for (int o = 1; o < 1024; o <<= 1) {
        int v = (t >= o) ? sp[t - o] : 0;
        __syncthreads();
        sp[t] += v;
        __syncthreads();
    }
    int run = (t == 0) ? 0 : sp[t - 1];
    for (int i = 0; i < CH; i++) {
        int idx = base + i;
        if (idx < N_NODES) { g_off[idx] = run; run += g_deg[idx]; }
    }
    if (t == 1023) g_off[N_NODES] = sp[1023];
}
__global__ void k_scatter(const int* __restrict__ ei) {
    int e = blockIdx.x * blockDim.x + threadIdx.x;
    if (e >= TOT_E) return;
    int s, d;
    if (e < N_EDGES) { s = ei[e]; d = ei[N_EDGES + e]; } else { s = d = e - N_EDGES; }
    int pos = g_off[d] + atomicAdd(&g_cursor[d], 1);
    g_csr_src[pos] = s;
}

// ---------------- W1 fp16 conversion (transpose to [n][k]) -----------------
__global__ void k_cvt_w(const float* __restrict__ W1) {
    int i = blockIdx.x * blockDim.x + threadIdx.x;
    if (i >= F1 * IN_CH) return;
    int n = i >> 7, k = i & 127;
    g_w1h[i] = __float2half_rn(W1[(size_t)k * F1 + n]);
}

// ======== GEMM1 via mma.sync fp16: H1 = x @ W1, fused att dots =============
#define LDT 136                       // SMEM row stride in fp16 (272B)
#define TILE_BYTES (128 * LDT * 2)    // 34816
#define SH_ATTS 0
#define SH_ATTD 2048
#define SH_A    4096
#define SH_B0   (SH_A + TILE_BYTES)
#define SH_B1   (SH_B0 + TILE_BYTES)
#define SH_TOTAL (SH_B1 + TILE_BYTES)   // 108544 B -> 2 CTAs/SM

__device__ __forceinline__ void copy_tile_async(uint32_t dst_sb,
                                                const __half* __restrict__ src,
                                                int tid) {
#pragma unroll
    for (int it = 0; it < 8; it++) {
        int f = it * 256 + tid;
        int r = f >> 4;
        int c16 = f & 15;
        uint32_t d = dst_sb + (uint32_t)r * (LDT * 2) + (uint32_t)c16 * 16;
        const void* s = src + (size_t)r * 128 + c16 * 8;
        asm volatile("cp.async.cg.shared.global [%0], [%1], 16;" :: "r"(d), "l"(s));
    }
}
__device__ __forceinline__ void load_A_f16(char* dst, const float* __restrict__ x,
                                           int m0, int tid) {
#pragma unroll
    for (int it = 0; it < 16; it++) {
        int f = it * 256 + tid;          // float4 id 0..4095
        int r = f >> 5;
        int c4 = (f & 31) * 4;
        int gm = m0 + r;
        float4 v = (gm < N_NODES) ? *(const float4*)(x + (size_t)gm * IN_CH + c4)
                                  : make_float4(0.f, 0.f, 0.f, 0.f);
        __half2 p0 = __floats2half2_rn(v.x, v.y);
        __half2 p1 = __floats2half2_rn(v.z, v.w);
        uint2 pk;
        pk.x = *(const uint32_t*)&p0;
        pk.y = *(const uint32_t*)&p1;
        *(uint2*)(dst + r * (LDT * 2) + c4 * 2) = pk;
    }
}

__global__ __launch_bounds__(256) void k_mma1(const float* __restrict__ x,
                                              const float* __restrict__ att_s,
                                              const float* __restrict__ att_d) {
    extern __shared__ char smem[];
    int tid = threadIdx.x;
    int wid = tid >> 5, lane = tid & 31;
    int wm = wid & 3;
    int wn = wid >> 2;
    int m0 = blockIdx.x * 128;
    uint32_t sb = smem_u32(smem);

    copy_tile_async(sb + SH_B0, g_w1h, tid);
    asm volatile("cp.async.commit_group;" ::: "memory");

    for (int i = tid; i < 512; i += 256) {
        ((float*)(smem + SH_ATTS))[i] = att_s[i];
        ((float*)(smem + SH_ATTD))[i] = att_d[i];
    }
    load_A_f16(smem + SH_A, x, m0, tid);

    uint32_t ab = sb + SH_A;
    uint32_t a_row_off[2], b_row_off[4];
#pragma unroll
    for (int mf = 0; mf < 2; mf++)
        a_row_off[mf] = (uint32_t)(wm * 32 + mf * 16 + (lane & 7) + ((lane >> 3) & 1) * 8) * (LDT * 2);
#pragma unroll
    for (int jj = 0; jj < 4; jj++)
        b_row_off[jj] = (uint32_t)(wn * 64 + jj * 16 + (lane & 7) + (lane >> 4) * 8) * (LDT * 2);
    uint32_t a_k_lane = ((uint32_t)(lane >> 4) * 8) * 2;
    uint32_t b_k_lane = ((uint32_t)((lane >> 3) & 1) * 8) * 2;

    const float* sas = (const float*)(smem + SH_ATTS);
    const float* sad = (const float*)(smem + SH_ATTD);

    for (int chunk = 0; chunk < 4; chunk++) {
        if (chunk < 3) {
            uint32_t nb = sb + (((chunk + 1) & 1) ? SH_B1 : SH_B0);
            copy_tile_async(nb, g_w1h + (size_t)(chunk + 1) * 128 * 128, tid);
            asm volatile("cp.async.commit_group;" ::: "memory");
            asm volatile("cp.async.wait_group 1;" ::: "memory");
        } else {
            asm volatile("cp.async.wait_group 0;" ::: "memory");
        }
        __syncthreads();

        uint32_t bb = sb + ((chunk & 1) ? SH_B1 : SH_B0);

        float acc[2][8][4];
#pragma unroll
        for (int mf = 0; mf < 2; mf++)
#pragma unroll
            for (int nf = 0; nf < 8; nf++)
#pragma unroll
                for (int q = 0; q < 4; q++) acc[mf][nf][q] = 0.f;

        for (int kb = 0; kb < 8; kb++) {
            uint32_t akoff = (uint32_t)(kb * 16) * 2 + a_k_lane;
            uint32_t bkoff = (uint32_t)(kb * 16) * 2 + b_k_lane;
            uint32_t afr[2][4], bfr[4][4];
#pragma unroll
            for (int mf = 0; mf < 2; mf++) ldsm4(afr[mf], ab + a_row_off[mf] + akoff);
#pragma unroll
            for (int jj = 0; jj < 4; jj++) ldsm4(bfr[jj], bb + b_row_off[jj] + bkoff);
#pragma unroll
            for (int mf = 0; mf < 2; mf++)
#pragma unroll
                for (int nf = 0; nf < 8; nf++)
                    mma16816(acc[mf][nf], afr[mf],
                             bfr[nf >> 1][(nf & 1) * 2], bfr[nf >> 1][(nf & 1) * 2 + 1]);
        }
        __syncthreads();   // done reading this B buffer (rewritten at chunk+2)

        int head = chunk * 2 + wn;
        float ps[2][2] = {}, pd[2][2] = {};
#pragma unroll
        for (int nf = 0; nf < 8; nf++) {
            int cl = nf * 8 + (lane & 3) * 2;
            int col = head * 64 + cl;
            float2 wa = *(const float2*)(sas + col);
            float2 wd = *(const float2*)(sad + col);
#pragma unroll
            for (int mf = 0; mf < 2; mf++)
#pragma unroll
                for (int rh = 0; rh < 2; rh++) {
                    float d0 = acc[mf][nf][rh * 2], d1 = acc[mf][nf][rh * 2 + 1];
                    int row = m0 + wm * 32 + mf * 16 + rh * 8 + (lane >> 2);
                    if (row < N_NODES)
                        *(__half2*)(g_H1h + (size_t)row * F1 + col) = __floats2half2_rn(d0, d1);
                    ps[mf][rh] += d0 * wa.x + d1 * wa.y;
                    pd[mf][rh] += d0 * wd.x + d1 * wd.y;
                }
        }
#pragma unroll
        for (int mf = 0; mf < 2; mf++)
#pragma unroll
            for (int rh = 0; rh < 2; rh++) {
                float s = ps[mf][rh], d = pd[mf][rh];
                s += __shfl_xor_sync(0xffffffffu, s, 1);
                s += __shfl_xor_sync(0xffffffffu, s, 2);
                d += __shfl_xor_sync(0xffffffffu, d, 1);
                d += __shfl_xor_sync(0xffffffffu, d, 2);
                int row = m0 + wm * 32 + mf * 16 + rh * 8 + (lane >> 2);
                if ((lane & 3) == 0 && row < N_NODES) {
                    g_as1[row * 8 + head] = s;
                    g_ad1[row * 8 + head] = d;
                }
            }
    }
}

// ---- layer-1 CSR aggregation, warp per dst, 2-edge unroll -----------------
__global__ __launch_bounds__(128) void k_agg1(const float* __restrict__ b1) {
    int d = (blockIdx.x * blockDim.x + threadIdx.x) >> 5;
    int lane = threadIdx.x & 31;
    if (d >= N_NODES) return;
    int beg = g_off[d], end = g_off[d + 1];
    float ad = (lane < HEADS) ? g_ad1[d * 8 + lane] : 0.f;
    float den = 0.f;
    float acc[2][8] = {};
    int hq = lane >> 3;                         // 0..3
    int k = beg;
    for (; k + 1 < end; k += 2) {
        int s0 = g_csr_src[k], s1 = g_csr_src[k + 1];
        float e0 = 0.f, e1 = 0.f;
        if (lane < HEADS) {
            e0 = __expf(lrelu(g_as1[s0 * 8 + lane] + ad));
            e1 = __expf(lrelu(g_as1[s1 * 8 + lane] + ad));
            den += e0 + e1;
        }
        const uint4* hp0 = (const uint4*)(g_H1h + (size_t)s0 * F1);
        const uint4* hp1 = (const uint4*)(g_H1h + (size_t)s1 * F1);
        uint4 v00 = hp0[lane], v01 = hp0[32 + lane];
        uint4 v10 = hp1[lane], v11 = hp1[32 + lane];
#pragma unroll
        for (int i = 0; i < 2; i++) {
            float w0 = __shfl_sync(0xffffffffu, e0, i * 4 + hq);
            float w1 = __shfl_sync(0xffffffffu, e1, i * 4 + hq);
            uint4 va = i ? v01 : v00;
            uint4 vb = i ? v11 : v10;
            const __half2* pa = (const __half2*)&va;
            const __half2* pb = (const __half2*)&vb;
#pragma unroll
            for (int j2 = 0; j2 < 4; j2++) {
                float2 fa = __half22float2(pa[j2]);
                float2 fb = __half22float2(pb[j2]);
                acc[i][j2 * 2]     += w0 * fa.x + w1 * fb.x;
                acc[i][j2 * 2 + 1] += w0 * fa.y + w1 * fb.y;
            }
        }
    }
    if (k < end) {
        int s = g_csr_src[k];
        float ee = 0.f;
        if (lane < HEADS) {
            ee = __expf(lrelu(g_as1[s * 8 + lane] + ad));
            den += ee;
        }
        const uint4* hp = (const uint4*)(g_H1h + (size_t)s * F1);
#pragma unroll
        for (int i = 0; i < 2; i++) {
            float w = __shfl_sync(0xffffffffu, ee, i * 4 + hq);
            uint4 v = hp[i * 32 + lane];
            const __half2* p2 = (const __half2*)&v;
#pragma unroll
            for (int j2 = 0; j2 < 4; j2++) {
                float2 f = __half22float2(p2[j2]);
                acc[i][j2 * 2]     += w * f.x;
                acc[i][j2 * 2 + 1] += w * f.y;
            }
        }
    }
    float t[8];
#pragma unroll
    for (int i = 0; i < 2; i++) {
        float dh = __shfl_sync(0xffffffffu, den, i * 4 + hq);
        float inv = 1.f / dh;
#pragma unroll
        for (int j = 0; j < 8; j++) acc[i][j] *= inv;
    }
#pragma unroll
    for (int j = 0; j < 8; j++) t[j] = acc[0][j] + acc[1][j];
#pragma unroll
    for (int j = 0; j < 8; j++) {
        t[j] += __shfl_xor_sync(0xffffffffu, t[j], 8);
        t[j] += __shfl_xor_sync(0xffffffffu, t[j], 16);
    }
    if (lane < 8) {
        int c0 = lane * 8;
        float4 b0 = *(const float4*)(b1 + c0);
        float4 b4 = *(const float4*)(b1 + c0 + 4);
        float o[8];
        o[0] = t[0] * 0.125f + b0.x; o[1] = t[1] * 0.125f + b0.y;
        o[2] = t[2] * 0.125f + b0.z; o[3] = t[3] * 0.125f + b0.w;
        o[4] = t[4] * 0.125f + b4.x; o[5] = t[5] * 0.125f + b4.y;
        o[6] = t[6] * 0.125f + b4.z; o[7] = t[7] * 0.125f + b4.w;
#pragma unroll
        for (int j = 0; j < 8; j++) o[j] = o[j] > 0.f ? o[j] : expm1f(o[j]);
        *(float4*)(g_X2 + (size_t)d * OUT_CH + c0)     = make_float4(o[0], o[1], o[2], o[3]);
        *(float4*)(g_X2 + (size_t)d * OUT_CH + c0 + 4) = make_float4(o[4], o[5], o[6], o[7]);
    }
}

// -------- GEMM2 + fused attention dots: H2 = X2 @ W2, as2/ad2 --------------
__global__ __launch_bounds__(256) void k_gemm2(const float* __restrict__ W2,
                                               const float* __restrict__ as2v,
                                               const float* __restrict__ ad2v) {
    __shared__ float ws[64 * 64];
    __shared__ float xs[16][64];
    __shared__ float sred[8][8];
    int tid = threadIdx.x;
    for (int i = tid; i < 64 * 64; i += 256) ws[i] = W2[i];
    int r0 = blockIdx.x * 16;
    for (int i = tid; i < 16 * 64; i += 256) {
        int r = i >> 6, c = i & 63;
        xs[r][c] = g_X2[(size_t)(r0 + r) * 64 + c];
    }
    __syncthreads();
    int c = tid & 63;
    int rg = tid >> 6;
    int warp = tid >> 5, lane = tid & 31;
    float acc[4] = {0.f, 0.f, 0.f, 0.f};
    for (int k = 0; k < 64; k++) {
        float w = ws[k * 64 + c];
#pragma unroll
        for (int j = 0; j < 4; j++) acc[j] += xs[rg * 4 + j][k] * w;
    }
    float sa = __ldg(as2v + c), da = __ldg(ad2v + c);
    float sp[4], dp[4];
#pragma unroll
    for (int j = 0; j < 4; j++) {
        g_H2h[(size_t)(r0 + rg * 4 + j) * 64 + c] = __float2half_rn(acc[j]);
        sp[j] = acc[j] * sa;
        dp[j] = acc[j] * da;
    }
#pragma unroll
    for (int o = 16; o; o >>= 1)
#pragma unroll
        for (int j = 0; j < 4; j++) {
            sp[j] += __shfl_xor_sync(0xffffffffu, sp[j], o);
            dp[j] += __shfl_xor_sync(0xffffffffu, dp[j], o);
        }
    if (lane == 0) {
#pragma unroll
        for (int j = 0; j < 4; j++) { sred[warp][j] = sp[j]; sred[warp][4 + j] = dp[j]; }
    }
    __syncthreads();
    if (tid < 32) {
        int rg2 = tid >> 3, j = (tid >> 1) & 3, sv = tid & 1;
        float v = sred[rg2 * 2][sv * 4 + j] + sred[rg2 * 2 + 1][sv * 4 + j];
        int row = r0 + rg2 * 4 + j;
        if (sv == 0) g_as2[row] = v; else g_ad2[row] = v;
    }
}

// ---- layer-2 CSR aggregation: split-warp, 2 edges in flight ---------------
__global__ __launch_bounds__(128) void k_agg2(const float* __restrict__ b2,
                                              float* __restrict__ out) {
    int d = (blockIdx.x * blockDim.x + threadIdx.x) >> 5;
    int lane = threadIdx.x & 31;
    if (d >= N_NODES) return;
    int beg = g_off[d], end = g_off[d + 1];
    int half = lane >> 4;
    int hl = lane & 15;
    float ad = g_ad2[d];
    float den = 0.f;
    float acc[4] = {0.f, 0.f, 0.f, 0.f};
    for (int k = beg + half; k < end; k += 2) {
        int s = g_csr_src[k];
        float ee = __expf(lrelu(g_as2[s] + ad));
        den += ee;
        uint2 v = ((const uint2*)(g_H2h + (size_t)s * 64))[hl];
        float2 f0 = __half22float2(*(const __half2*)&v.x);
        float2 f1 = __half22float2(*(const __half2*)&v.y);
        acc[0] += ee * f0.x; acc[1] += ee * f0.y;
        acc[2] += ee * f1.x; acc[3] += ee * f1.y;
    }
    den += __shfl_xor_sync(0xffffffffu, den, 16);
#pragma unroll
    for (int j = 0; j < 4; j++) acc[j] += __shfl_xor_sync(0xffffffffu, acc[j], 16);
    if (lane < 16) {
        float inv = 1.f / den;
        float4 bb = *(const float4*)(b2 + hl * 4);
        *(float4*)(out + (size_t)d * 64 + hl * 4) =
            make_float4(acc[0] * inv + bb.x, acc[1] * inv + bb.y,
                        acc[2] * inv + bb.z, acc[3] * inv + bb.w);
    }
}

// ---------------------------------------------------------------------------
extern "C" void kernel_launch(void* const* d_in, const int* in_sizes, int n_in,
                              void* d_out, int out_size) {
    const float* x   = (const float*)d_in[0];
    const int*   ei  = (const int*)  d_in[1];
    const float* W1  = (const float*)d_in[2];
    const float* as1 = (const float*)d_in[3];
    const float* ad1 = (const float*)d_in[4];
    const float* b1  = (const float*)d_in[5];
    const float* W2  = (const float*)d_in[6];
    const float* as2 = (const float*)d_in[7];
    const float* ad2 = (const float*)d_in[8];
    const float* b2  = (const float*)d_in[9];
    float* out = (float*)d_out;

    static cudaStream_t s1;
    static cudaEvent_t ev0, ev1;
    static int inited = 0;
    if (!inited) {
        cudaFuncSetAttribute(k_mma1, cudaFuncAttributeMaxDynamicSharedMemorySize, SH_TOTAL);
        cudaStreamCreateWithFlags(&s1, cudaStreamNonBlocking);
        cudaEventCreateWithFlags(&ev0, cudaEventDisableTiming);
        cudaEventCreateWithFlags(&ev1, cudaEventDisableTiming);
        inited = 1;
    }

    // fork: CSR build on side stream, concurrent with cvt_w + mma1
    cudaEventRecord(ev0, 0);
    cudaStreamWaitEvent(s1, ev0, 0);
    k_init<<<(N_NODES + 255) / 256, 256, 0, s1>>>();
    k_hist<<<(TOT_E + 255) / 256, 256, 0, s1>>>(ei);
    k_scan<<<1, 1024, 0, s1>>>();
    k_scatter<<<(TOT_E + 255) / 256, 256, 0, s1>>>(ei);
    cudaEventRecord(ev1, s1);

    k_cvt_w<<<(F1 * IN_CH + 255) / 256, 256>>>(W1);
    k_mma1<<<M_TILES, 256, SH_TOTAL>>>(x, as1, ad1);

    // join: aggregation needs both CSR and H1
    cudaStreamWaitEvent(0, ev1, 0);
    k_agg1<<<(N_NODES * 32 + 127) / 128, 128>>>(b1);

    // layer 2
    k_gemm2<<<N_NODES / 16, 256>>>(W2, as2, ad2);
    k_agg2<<<(N_NODES * 32 + 127) / 128, 128>>>(b2, out);
}

// round 14
// speedup vs baseline: 1.4345x; 1.4345x over previous
#include <cuda_runtime.h>
#include <cuda_fp16.h>
#include <math.h>
#include <stdint.h>

#define N_NODES 50000
#define N_EDGES 400000
#define TOT_E   (N_EDGES + N_NODES)
#define IN_CH   128
#define OUT_CH  64
#define HEADS   8
#define F1      (HEADS * OUT_CH)      // 512
#define M_TILES 391

// ---------------- device scratch -------------------------------------------
__device__ __align__(16) __half g_H1h[N_NODES * F1];     // layer-1 features, fp16
__device__ __align__(16) float g_as1[N_NODES * HEADS];
__device__ __align__(16) float g_ad1[N_NODES * HEADS];
__device__ __align__(16) float g_X2[N_NODES * OUT_CH];
__device__ __align__(16) __half g_H2h[N_NODES * OUT_CH];
__device__ __align__(16) float g_as2[N_NODES];
__device__ __align__(16) float g_ad2[N_NODES];
__device__ __align__(16) __half g_w1h[F1 * IN_CH];       // [n][k] transposed, fp16
// CSR by destination
__device__ int g_deg[N_NODES];
__device__ int g_cursor[N_NODES];
__device__ int g_off[N_NODES + 1];
__device__ int g_csr_src[TOT_E];

__device__ __forceinline__ float lrelu(float v) { return v > 0.f ? v : 0.2f * v; }

__device__ __forceinline__ uint32_t smem_u32(const void* p) {
    uint32_t a;
    asm("{ .reg .u64 t; cvta.to.shared.u64 t, %1; cvt.u32.u64 %0, t; }"
        : "=r"(a) : "l"(p));
    return a;
}
__device__ __forceinline__ void ldsm4(uint32_t* r, uint32_t addr) {
    asm volatile("ldmatrix.sync.aligned.m8n8.x4.shared.b16 {%0,%1,%2,%3}, [%4];"
                 : "=r"(r[0]), "=r"(r[1]), "=r"(r[2]), "=r"(r[3]) : "r"(addr));
}
__device__ __forceinline__ void mma16816(float* d, const uint32_t* a,
                                         const uint32_t b0, const uint32_t b1) {
    asm volatile("mma.sync.aligned.m16n8k16.row.col.f32.f16.f16.f32 "
                 "{%0,%1,%2,%3}, {%4,%5,%6,%7}, {%8,%9}, {%0,%1,%2,%3};"
                 : "+f"(d[0]), "+f"(d[1]), "+f"(d[2]), "+f"(d[3])
                 : "r"(a[0]), "r"(a[1]), "r"(a[2]), "r"(a[3]), "r"(b0), "r"(b1));
}

// ---------------- init + CSR build -----------------------------------------
__global__ void k_init() {
    int i = blockIdx.x * blockDim.x + threadIdx.x;
    if (i < N_NODES) { g_deg[i] = 0; g_cursor[i] = 0; }
}
__global__ void k_hist(const int* __restrict__ ei) {
    int e = blockIdx.x * blockDim.x + threadIdx.x;
    if (e >= TOT_E) return;
    int d = (e < N_EDGES) ? ei[N_EDGES + e] : e - N_EDGES;
    atomicAdd(&g_deg[d], 1);
}
__global__ __launch_bounds__(1024) void k_scan() {
    __shared__ int sp[1024];
    int t = threadIdx.x;
    const int CH = (N_NODES + 1023) / 1024;
    int base = t * CH, s = 0;
    for (int i = 0; i < CH; i++) { int idx = base + i; if (idx < N_NODES) s += g_deg[idx]; }
    sp[t] = s;
    __syncthreads();
    for (int o = 1; o < 1024; o <<= 1) {
        int v = (t >= o) ? sp[t - o] : 0;
        __syncthreads();
        sp[t] += v;
        __syncthreads();
    }
    int run = (t == 0) ? 0 : sp[t - 1];
    for (int i = 0; i < CH; i++) {
        int idx = base + i;
        if (idx < N_NODES) { g_off[idx] = run; run += g_deg[idx]; }
    }
    if (t == 1023) g_off[N_NODES] = sp[1023];
}
__global__ void k_scatter(const int* __restrict__ ei) {
    int e = blockIdx.x * blockDim.x + threadIdx.x;
    if (e >= TOT_E) return;
    int s, d;
    if (e < N_EDGES) { s = ei[e]; d = ei[N_EDGES + e]; } else { s = d = e - N_EDGES; }
    int pos = g_off[d] + atomicAdd(&g_cursor[d], 1);
    g_csr_src[pos] = s;
}

// ---------------- W1 fp16 conversion (transpose to [n][k]) -----------------
__global__ void k_cvt_w(const float* __restrict__ W1) {
    int i = blockIdx.x * blockDim.x + threadIdx.x;
    if (i >= F1 * IN_CH) return;
    int n = i >> 7, k = i & 127;
    g_w1h[i] = __float2half_rn(W1[(size_t)k * F1 + n]);
}

// ======== GEMM1 via mma.sync fp16: H1 = x @ W1, fused att dots =============
#define LDT 136                       // SMEM row stride in fp16 (272B)
#define TILE_BYTES (128 * LDT * 2)    // 34816
#define SH_ATTS 0
#define SH_ATTD 2048
#define SH_A    4096
#define SH_B0   (SH_A + TILE_BYTES)
#define SH_B1   (SH_B0 + TILE_BYTES)
#define SH_TOTAL (SH_B1 + TILE_BYTES)   // 108544 B -> 2 CTAs/SM

__device__ __forceinline__ void copy_tile_async(uint32_t dst_sb,
                                                const __half* __restrict__ src,
                                                int tid) {
#pragma unroll
    for (int it = 0; it < 8; it++) {
        int f = it * 256 + tid;
        int r = f >> 4;
        int c16 = f & 15;
        uint32_t d = dst_sb + (uint32_t)r * (LDT * 2) + (uint32_t)c16 * 16;
        const void* s = src + (size_t)r * 128 + c16 * 8;
        asm volatile("cp.async.cg.shared.global [%0], [%1], 16;" :: "r"(d), "l"(s));
    }
}
// load fp32 x tile, convert to fp16 SMEM tile
__device__ __forceinline__ void load_A_f16(char* dst, const float* __restrict__ x,
                                           int m0, int tid) {
#pragma unroll
    for (int it = 0; it < 16; it++) {
        int f = it * 256 + tid;          // float4 id 0..4095
        int r = f >> 5;
        int c4 = (f & 31) * 4;
        int gm = m0 + r;
        float4 v = (gm < N_NODES) ? *(const float4*)(x + (size_t)gm * IN_CH + c4)
                                  : make_float4(0.f, 0.f, 0.f, 0.f);
        __half2 p0 = __floats2half2_rn(v.x, v.y);
        __half2 p1 = __floats2half2_rn(v.z, v.w);
        uint2 pk;
        pk.x = *(const uint32_t*)&p0;
        pk.y = *(const uint32_t*)&p1;
        *(uint2*)(dst + r * (LDT * 2) + c4 * 2) = pk;
    }
}

__global__ __launch_bounds__(256) void k_mma1(const float* __restrict__ x,
                                              const float* __restrict__ att_s,
                                              const float* __restrict__ att_d) {
    extern __shared__ char smem[];
    int tid = threadIdx.x;
    int wid = tid >> 5, lane = tid & 31;
    int wm = wid & 3;
    int wn = wid >> 2;
    int m0 = blockIdx.x * 128;
    uint32_t sb = smem_u32(smem);

    copy_tile_async(sb + SH_B0, g_w1h, tid);
    asm volatile("cp.async.commit_group;" ::: "memory");

    for (int i = tid; i < 512; i += 256) {
        ((float*)(smem + SH_ATTS))[i] = att_s[i];
        ((float*)(smem + SH_ATTD))[i] = att_d[i];
    }
    load_A_f16(smem + SH_A, x, m0, tid);

    uint32_t ab = sb + SH_A;
    uint32_t a_row_off[2], b_row_off[4];
#pragma unroll
    for (int mf = 0; mf < 2; mf++)
        a_row_off[mf] = (uint32_t)(wm * 32 + mf * 16 + (lane & 7) + ((lane >> 3) & 1) * 8) * (LDT * 2);
#pragma unroll
    for (int jj = 0; jj < 4; jj++)
        b_row_off[jj] = (uint32_t)(wn * 64 + jj * 16 + (lane & 7) + (lane >> 4) * 8) * (LDT * 2);
    uint32_t a_k_lane = ((uint32_t)(lane >> 4) * 8) * 2;
    uint32_t b_k_lane = ((uint32_t)((lane >> 3) & 1) * 8) * 2;

    const float* sas = (const float*)(smem + SH_ATTS);
    const float* sad = (const float*)(smem + SH_ATTD);

    for (int chunk = 0; chunk < 4; chunk++) {
        if (chunk < 3) {
            uint32_t nb = sb + (((chunk + 1) & 1) ? SH_B1 : SH_B0);
            copy_tile_async(nb, g_w1h + (size_t)(chunk + 1) * 128 * 128, tid);
            asm volatile("cp.async.commit_group;" ::: "memory");
            asm volatile("cp.async.wait_group 1;" ::: "memory");
        } else {
            asm volatile("cp.async.wait_group 0;" ::: "memory");
        }
        __syncthreads();

        uint32_t bb = sb + ((chunk & 1) ? SH_B1 : SH_B0);

        float acc[2][8][4];
#pragma unroll
        for (int mf = 0; mf < 2; mf++)
#pragma unroll
            for (int nf = 0; nf < 8; nf++)
#pragma unroll
                for (int q = 0; q < 4; q++) acc[mf][nf][q] = 0.f;

        for (int kb = 0; kb < 8; kb++) {
            uint32_t akoff = (uint32_t)(kb * 16) * 2 + a_k_lane;
            uint32_t bkoff = (uint32_t)(kb * 16) * 2 + b_k_lane;
            uint32_t afr[2][4], bfr[4][4];
#pragma unroll
            for (int mf = 0; mf < 2; mf++) ldsm4(afr[mf], ab + a_row_off[mf] + akoff);
#pragma unroll
            for (int jj = 0; jj < 4; jj++) ldsm4(bfr[jj], bb + b_row_off[jj] + bkoff);
#pragma unroll
            for (int mf = 0; mf < 2; mf++)
#pragma unroll
                for (int nf = 0; nf < 8; nf++)
                    mma16816(acc[mf][nf], afr[mf],
                             bfr[nf >> 1][(nf & 1) * 2], bfr[nf >> 1][(nf & 1) * 2 + 1]);
        }
        __syncthreads();   // done reading this B buffer (rewritten at chunk+2)

        int head = chunk * 2 + wn;
        float ps[2][2] = {}, pd[2][2] = {};
#pragma unroll
        for (int nf = 0; nf < 8; nf++) {
            int cl = nf * 8 + (lane & 3) * 2;
            int col = head * 64 + cl;
            float2 wa = *(const float2*)(sas + col);
            float2 wd = *(const float2*)(sad + col);
#pragma unroll
            for (int mf = 0; mf < 2; mf++)
#pragma unroll
                for (int rh = 0; rh < 2; rh++) {
                    float d0 = acc[mf][nf][rh * 2], d1 = acc[mf][nf][rh * 2 + 1];
                    int row = m0 + wm * 32 + mf * 16 + rh * 8 + (lane >> 2);
                    if (row < N_NODES)
                        *(__half2*)(g_H1h + (size_t)row * F1 + col) = __floats2half2_rn(d0, d1);
                    ps[mf][rh] += d0 * wa.x + d1 * wa.y;
                    pd[mf][rh] += d0 * wd.x + d1 * wd.y;
                }
        }
#pragma unroll
        for (int mf = 0; mf < 2; mf++)
#pragma unroll
            for (int rh = 0; rh < 2; rh++) {
                float s = ps[mf][rh], d = pd[mf][rh];
                s += __shfl_xor_sync(0xffffffffu, s, 1);
                s += __shfl_xor_sync(0xffffffffu, s, 2);
                d += __shfl_xor_sync(0xffffffffu, d, 1);
                d += __shfl_xor_sync(0xffffffffu, d, 2);
                int row = m0 + wm * 32 + mf * 16 + rh * 8 + (lane >> 2);
                if ((lane & 3) == 0 && row < N_NODES) {
                    g_as1[row * 8 + head] = s;
                    g_ad1[row * 8 + head] = d;
                }
            }
    }
}

// ---- layer-1 CSR aggregation, warp per dst, 2-edge unroll -----------------
__global__ __launch_bounds__(256) void k_agg1(const float* __restrict__ b1) {
    int d = (blockIdx.x * blockDim.x + threadIdx.x) >> 5;
    int lane = threadIdx.x & 31;
    if (d >= N_NODES) return;
    int beg = g_off[d], end = g_off[d + 1];
    float ad = (lane < HEADS) ? g_ad1[d * 8 + lane] : 0.f;
    float den = 0.f;
    float acc[2][8] = {};
    int hq = lane >> 3;                         // 0..3
    int k = beg;
    for (; k + 1 < end; k += 2) {
        int s0 = g_csr_src[k], s1 = g_csr_src[k + 1];
        float e0 = 0.f, e1 = 0.f;
        if (lane < HEADS) {
            e0 = __expf(lrelu(g_as1[s0 * 8 + lane] + ad));
            e1 = __expf(lrelu(g_as1[s1 * 8 + lane] + ad));
            den += e0 + e1;
        }
        const uint4* hp0 = (const uint4*)(g_H1h + (size_t)s0 * F1);
        const uint4* hp1 = (const uint4*)(g_H1h + (size_t)s1 * F1);
        uint4 v00 = hp0[lane], v01 = hp0[32 + lane];
        uint4 v10 = hp1[lane], v11 = hp1[32 + lane];
#pragma unroll
        for (int i = 0; i < 2; i++) {
            float w0 = __shfl_sync(0xffffffffu, e0, i * 4 + hq);
            float w1 = __shfl_sync(0xffffffffu, e1, i * 4 + hq);
            uint4 va = i ? v01 : v00;
            uint4 vb = i ? v11 : v10;
            const __half2* pa = (const __half2*)&va;
            const __half2* pb = (const __half2*)&vb;
#pragma unroll
            for (int j2 = 0; j2 < 4; j2++) {
                float2 fa = __half22float2(pa[j2]);
                float2 fb = __half22float2(pb[j2]);
                acc[i][j2 * 2]     += w0 * fa.x + w1 * fb.x;
                acc[i][j2 * 2 + 1] += w0 * fa.y + w1 * fb.y;
            }
        }
    }
    if (k < end) {
        int s = g_csr_src[k];
        float ee = 0.f;
        if (lane < HEADS) {
            ee = __expf(lrelu(g_as1[s * 8 + lane] + ad));
            den += ee;
        }
        const uint4* hp = (const uint4*)(g_H1h + (size_t)s * F1);
#pragma unroll
        for (int i = 0; i < 2; i++) {
            float w = __shfl_sync(0xffffffffu, ee, i * 4 + hq);
            uint4 v = hp[i * 32 + lane];
            const __half2* p2 = (const __half2*)&v;
#pragma unroll
            for (int j2 = 0; j2 < 4; j2++) {
                float2 f = __half22float2(p2[j2]);
                acc[i][j2 * 2]     += w * f.x;
                acc[i][j2 * 2 + 1] += w * f.y;
            }
        }
    }
    float t[8];
#pragma unroll
    for (int i = 0; i < 2; i++) {
        float dh = __shfl_sync(0xffffffffu, den, i * 4 + hq);
        float inv = 1.f / dh;
#pragma unroll
        for (int j = 0; j < 8; j++) acc[i][j] *= inv;
    }
#pragma unroll
    for (int j = 0; j < 8; j++) t[j] = acc[0][j] + acc[1][j];
#pragma unroll
    for (int j = 0; j < 8; j++) {
        t[j] += __shfl_xor_sync(0xffffffffu, t[j], 8);
        t[j] += __shfl_xor_sync(0xffffffffu, t[j], 16);
    }
    if (lane < 8) {
        int c0 = lane * 8;
        float4 b0 = *(const float4*)(b1 + c0);
        float4 b4 = *(const float4*)(b1 + c0 + 4);
        float o[8];
        o[0] = t[0] * 0.125f + b0.x; o[1] = t[1] * 0.125f + b0.y;
        o[2] = t[2] * 0.125f + b0.z; o[3] = t[3] * 0.125f + b0.w;
        o[4] = t[4] * 0.125f + b4.x; o[5] = t[5] * 0.125f + b4.y;
        o[6] = t[6] * 0.125f + b4.z; o[7] = t[7] * 0.125f + b4.w;
#pragma unroll
        for (int j = 0; j < 8; j++) o[j] = o[j] > 0.f ? o[j] : expm1f(o[j]);
        *(float4*)(g_X2 + (size_t)d * OUT_CH + c0)     = make_float4(o[0], o[1], o[2], o[3]);
        *(float4*)(g_X2 + (size_t)d * OUT_CH + c0 + 4) = make_float4(o[4], o[5], o[6], o[7]);
    }
}

// -------- GEMM2 + fused attention dots: H2 = X2 @ W2, as2/ad2 --------------
__global__ __launch_bounds__(256) void k_gemm2(const float* __restrict__ W2,
                                               const float* __restrict__ as2v,
                                               const float* __restrict__ ad2v) {
    __shared__ float ws[64 * 64];
    __shared__ float xs[16][64];
    __shared__ float sred[8][8];
    int tid = threadIdx.x;
    for (int i = tid; i < 64 * 64; i += 256) ws[i] = W2[i];
    int r0 = blockIdx.x * 16;
    for (int i = tid; i < 16 * 64; i += 256) {
        int r = i >> 6, c = i & 63;
        xs[r][c] = g_X2[(size_t)(r0 + r) * 64 + c];
    }
    __syncthreads();
    int c = tid & 63;
    int rg = tid >> 6;
    int warp = tid >> 5, lane = tid & 31;
    float acc[4] = {0.f, 0.f, 0.f, 0.f};
    for (int k = 0; k < 64; k++) {
        float w = ws[k * 64 + c];
#pragma unroll
        for (int j = 0; j < 4; j++) acc[j] += xs[rg * 4 + j][k] * w;
    }
    float sa = __ldg(as2v + c), da = __ldg(ad2v + c);
    float sp[4], dp[4];
#pragma unroll
    for (int j = 0; j < 4; j++) {
        g_H2h[(size_t)(r0 + rg * 4 + j) * 64 + c] = __float2half_rn(acc[j]);
        sp[j] = acc[j] * sa;
        dp[j] = acc[j] * da;
    }
#pragma unroll
    for (int o = 16; o; o >>= 1)
#pragma unroll
        for (int j = 0; j < 4; j++) {
            sp[j] += __shfl_xor_sync(0xffffffffu, sp[j], o);
            dp[j] += __shfl_xor_sync(0xffffffffu, dp[j], o);
        }
    if (lane == 0) {
#pragma unroll
        for (int j = 0; j < 4; j++) { sred[warp][j] = sp[j]; sred[warp][4 + j] = dp[j]; }
    }
    __syncthreads();
    if (tid < 32) {
        int rg2 = tid >> 3, j = (tid >> 1) & 3, sv = tid & 1;
        float v = sred[rg2 * 2][sv * 4 + j] + sred[rg2 * 2 + 1][sv * 4 + j];
        int row = r0 + rg2 * 4 + j;
        if (sv == 0) g_as2[row] = v; else g_ad2[row] = v;
    }
}

// ---- layer-2 CSR aggregation: split-warp, 2 edges in flight ---------------
__global__ __launch_bounds__(256) void k_agg2(const float* __restrict__ b2,
                                              float* __restrict__ out) {
    int d = (blockIdx.x * blockDim.x + threadIdx.x) >> 5;
    int lane = threadIdx.x & 31;
    if (d >= N_NODES) return;
    int beg = g_off[d], end = g_off[d + 1];
    int half = lane >> 4;
    int hl = lane & 15;
    float ad = g_ad2[d];
    float den = 0.f;
    float acc[4] = {0.f, 0.f, 0.f, 0.f};
    for (int k = beg + half; k < end; k += 2) {
        int s = g_csr_src[k];
        float ee = __expf(lrelu(g_as2[s] + ad));
        den += ee;
        uint2 v = ((const uint2*)(g_H2h + (size_t)s * 64))[hl];
        float2 f0 = __half22float2(*(const __half2*)&v.x);
        float2 f1 = __half22float2(*(const __half2*)&v.y);
        acc[0] += ee * f0.x; acc[1] += ee * f0.y;
        acc[2] += ee * f1.x; acc[3] += ee * f1.y;
    }
    den += __shfl_xor_sync(0xffffffffu, den, 16);
#pragma unroll
    for (int j = 0; j < 4; j++) acc[j] += __shfl_xor_sync(0xffffffffu, acc[j], 16);
    if (lane < 16) {
        float inv = 1.f / den;
        float4 bb = *(const float4*)(b2 + hl * 4);
        *(float4*)(out + (size_t)d * 64 + hl * 4) =
            make_float4(acc[0] * inv + bb.x, acc[1] * inv + bb.y,
                        acc[2] * inv + bb.z, acc[3] * inv + bb.w);
    }
}

// ---------------------------------------------------------------------------
extern "C" void kernel_launch(void* const* d_in, const int* in_sizes, int n_in,
                              void* d_out, int out_size) {
    const float* x   = (const float*)d_in[0];
    const int*   ei  = (const int*)  d_in[1];
    const float* W1  = (const float*)d_in[2];
    const float* as1 = (const float*)d_in[3];
    const float* ad1 = (const float*)d_in[4];
    const float* b1  = (const float*)d_in[5];
    const float* W2  = (const float*)d_in[6];
    const float* as2 = (const float*)d_in[7];
    const float* ad2 = (const float*)d_in[8];
    const float* b2  = (const float*)d_in[9];
    float* out = (float*)d_out;

    static cudaStream_t s1;
    static cudaEvent_t ev0, ev1;
    static int inited = 0;
    if (!inited) {
        cudaFuncSetAttribute(k_mma1, cudaFuncAttributeMaxDynamicSharedMemorySize, SH_TOTAL);
        cudaStreamCreateWithFlags(&s1, cudaStreamNonBlocking);
        cudaEventCreateWithFlags(&ev0, cudaEventDisableTiming);
        cudaEventCreateWithFlags(&ev1, cudaEventDisableTiming);
        inited = 1;
    }

    // fork: CSR build on side stream, concurrent with cvt_w + mma1
    cudaEventRecord(ev0, 0);
    cudaStreamWaitEvent(s1, ev0, 0);
    k_init<<<(N_NODES + 255) / 256, 256, 0, s1>>>();
    k_hist<<<(TOT_E + 255) / 256, 256, 0, s1>>>(ei);
    k_scan<<<1, 1024, 0, s1>>>();
    k_scatter<<<(TOT_E + 255) / 256, 256, 0, s1>>>(ei);
    cudaEventRecord(ev1, s1);

    k_cvt_w<<<(F1 * IN_CH + 255) / 256, 256>>>(W1);
    k_mma1<<<M_TILES, 256, SH_TOTAL>>>(x, as1, ad1);

    // join: aggregation needs both CSR and H1
    cudaStreamWaitEvent(0, ev1, 0);
    k_agg1<<<(N_NODES * 32 + 255) / 256, 256>>>(b1);

    // layer 2
    k_gemm2<<<N_NODES / 16, 256>>>(W2, as2, ad2);
    k_agg2<<<(N_NODES * 32 + 255) / 256, 256>>>(b2, out);
}